// round 11
// baseline (speedup 1.0000x reference)
#include <cuda_runtime.h>
#include <cuda_bf16.h>
#include <cstdint>

#define Bc 8
#define Hc 160
#define Wc 160
#define HWc (Hc*Wc)

typedef unsigned long long ull;

// scratch (no allocations allowed)
__device__ float g_xt[(size_t)Bc*HWc*64];        // x transposed to [b][hw][c]
__device__ uint2 g_bfrag_hi[9*4*8*32];           // main B frags bf16 hi [k][kstep][ntile][lane]
__device__ uint2 g_bfrag_lo[9*4*8*32];           // main B frags bf16 lo
__device__ uint2 g_bfragO_hi[9*4*3*32];          // offset-conv B frags hi
__device__ uint2 g_bfragO_lo[9*4*3*32];          // offset-conv B frags lo
__device__ float g_inv[64];
__device__ float g_bias2[64];

__device__ __forceinline__ uint32_t smem_u32(const void* p) {
    uint32_t a;
    asm("{ .reg .u64 t; cvta.to.shared.u64 t, %1; cvt.u32.u64 %0, t; }" : "=r"(a) : "l"(p));
    return a;
}
__device__ __forceinline__ unsigned sw128(unsigned off) {
    return off ^ ((off >> 3) & 0x70);
}
__device__ __forceinline__ void ldsm4(uint32_t* r, uint32_t addr) {
    asm volatile("ldmatrix.sync.aligned.m8n8.x4.shared.b16 {%0,%1,%2,%3}, [%4];"
        : "=r"(r[0]), "=r"(r[1]), "=r"(r[2]), "=r"(r[3]) : "r"(addr));
}
__device__ __forceinline__ void mma16816(float* c, const uint32_t* a, const uint2 b) {
    asm volatile("mma.sync.aligned.m16n8k16.row.col.f32.bf16.bf16.f32 "
        "{%0,%1,%2,%3}, {%4,%5,%6,%7}, {%8,%9}, {%0,%1,%2,%3};"
        : "+f"(c[0]), "+f"(c[1]), "+f"(c[2]), "+f"(c[3])
        : "r"(a[0]), "r"(a[1]), "r"(a[2]), "r"(a[3]), "r"(b.x), "r"(b.y));
}
// pack (x,y) -> bf16x2 hi + residual bf16x2 lo
__device__ __forceinline__ void split2(float x, float y, uint32_t& hv, uint32_t& lv) {
    asm("cvt.rn.bf16x2.f32 %0, %1, %2;" : "=r"(hv) : "f"(y), "f"(x));
    float hx = __uint_as_float(hv << 16);
    float hy = __uint_as_float(hv & 0xffff0000u);
    float rx = x - hx, ry = y - hy;
    asm("cvt.rn.bf16x2.f32 %0, %1, %2;" : "=r"(lv) : "f"(ry), "f"(rx));
}

// named barriers: FULL0=1, FULL1=2, EMPTY0=3, EMPTY1=4, PROD=5
#define BAR_SYNC_ALL(id)   asm volatile("bar.sync %0, 512;"   :: "r"(id) : "memory")
#define BAR_ARRIVE_ALL(id) asm volatile("bar.arrive %0, 512;" :: "r"(id) : "memory")
#define BAR_SYNC_PROD()    asm volatile("bar.sync 5, 256;"    ::: "memory")

// dynamic smem layout (bytes): double-buffered A, then offsets, then meta
#define SM_A(b)    ((b)*65536)             // A hi: 256 rows x 128 B (SW128)
#define SM_ALO(b)  ((b)*65536 + 32768)     // A lo
#define SM_OFF     131072                  // float[18][256]
#define SM_WT      149504                  // float[2][4][256]
#define SM_IDX     157696                  // int[2][4][256]
#define SM_TOTAL   165888

// ---------------------------------------------------------------------------
// prep: fold BN; split w_dcn AND w_off to bf16 hi/lo in mma B-fragment layout.
// ---------------------------------------------------------------------------
__global__ void prep_kernel(const float* __restrict__ w_dcn,
                            const float* __restrict__ b_dcn,
                            const float* __restrict__ w_off,
                            const float* __restrict__ gamma,
                            const float* __restrict__ beta,
                            const float* __restrict__ run_mean,
                            const float* __restrict__ run_var) {
    int k = blockIdx.x;
    int part = blockIdx.y;
    int t = threadIdx.x;
    {
        int e = part*256 + t;
        int lane  = e & 31;
        int ntile = (e >> 5) & 7;
        int kstep = e >> 8;
        int o  = ntile*8 + (lane >> 2);
        int c0 = kstep*16 + 2*(lane & 3);
        float w00 = w_dcn[o*576 + (c0  )*9 + k];
        float w01 = w_dcn[o*576 + (c0+1)*9 + k];
        float w10 = w_dcn[o*576 + (c0+8)*9 + k];
        float w11 = w_dcn[o*576 + (c0+9)*9 + k];
        uint32_t h0, l0, h1, l1;
        split2(w00, w01, h0, l0);
        split2(w10, w11, h1, l1);
        int idx = ((k*4 + kstep)*8 + ntile)*32 + lane;
        g_bfrag_hi[idx] = make_uint2(h0, h1);
        g_bfrag_lo[idx] = make_uint2(l0, l1);
    }
    {
        int e = part*256 + t;
        if (e < 384) {
            int lane  = e & 31;
            int ntile = (e >> 5) % 3;
            int kstep = e / 96;
            int o  = ntile*8 + (lane >> 2);
            int c0 = kstep*16 + 2*(lane & 3);
            float w00 = 0.f, w01 = 0.f, w10 = 0.f, w11 = 0.f;
            if (o < 18) {
                w00 = w_off[o*576 + (c0  )*9 + k];
                w01 = w_off[o*576 + (c0+1)*9 + k];
                w10 = w_off[o*576 + (c0+8)*9 + k];
                w11 = w_off[o*576 + (c0+9)*9 + k];
            }
            uint32_t h0, l0, h1, l1;
            split2(w00, w01, h0, l0);
            split2(w10, w11, h1, l1);
            int idx = ((k*4 + kstep)*3 + ntile)*32 + lane;
            g_bfragO_hi[idx] = make_uint2(h0, h1);
            g_bfragO_lo[idx] = make_uint2(l0, l1);
        }
    }
    if (k == 0 && part == 0 && t < 64) {
        float iv = gamma[t] * rsqrtf(run_var[t] + 1e-5f);
        g_inv[t] = iv;
        g_bias2[t] = b_dcn[t]*iv + beta[t] - run_mean[t]*iv;
    }
}

// ---------------------------------------------------------------------------
// transpose x: [b][c][hw] -> [b][hw][c]
// ---------------------------------------------------------------------------
__global__ __launch_bounds__(256) void transpose_kernel(const float* __restrict__ x) {
    __shared__ float sm[64*65];
    int b   = blockIdx.y;
    int hw0 = blockIdx.x * 64;
    int t   = threadIdx.x;
    const float* xb = x + (size_t)b*64*HWc;
    #pragma unroll
    for (int i = 0; i < 16; i++) {
        int c = i*4 + (t>>6);
        int j = t & 63;
        sm[c*65 + j] = xb[(size_t)c*HWc + hw0 + j];
    }
    __syncthreads();
    float* ob = g_xt + ((size_t)b*HWc + hw0)*64;
    #pragma unroll
    for (int i = 0; i < 16; i++) {
        int hw = i*4 + (t>>6);
        int c  = t & 63;
        ob[hw*64 + c] = sm[c*65 + hw];
    }
}

// ---------------------------------------------------------------------------
// fused, warp-specialized: 512 threads.
// Phase 1 (all warps): offset conv implicit GEMM (full bf16 hi/lo 3-pass)
//   -> offsets in smem.
// Phase 2: warps 0-7 = producers (bilinear gather -> bf16 hi/lo A tiles,
//   double-buffered by k); warps 8-15 = consumers (ldsm + B-frag ldg +
//   3-pass mma, fp32 acc) -> BN + ReLU.  Named-barrier FULL/EMPTY pipeline.
// Block = 256 px (8 rows x 32 cols).
// ---------------------------------------------------------------------------
__global__ __launch_bounds__(512, 1) void fused_kernel(
        const float* __restrict__ b_off,
        float* __restrict__ out) {
    extern __shared__ char smem[];
    const uint32_t sbase = smem_u32(smem);
    float* s_off = (float*)(smem + SM_OFF);   // [18][256]
    float* s_wt  = (float*)(smem + SM_WT);    // [2][4][256]
    int*   s_idx = (int*)(smem + SM_IDX);     // [2][4][256]

    const int t    = threadIdx.x;
    const int wid  = t >> 5;
    const int lane = t & 31;
    const int b    = blockIdx.z;
    const int h0   = blockIdx.y * 8;
    const int w0   = blockIdx.x * 32;

    const float* xtb = g_xt + (size_t)b*HWc*64;

    const int prow = lane >> 2;
    const int ocol = 2*(lane & 3);

    // ============================ phase 1: offset conv =====================
    // all 16 warps: 16 rows each; A-build over 512 threads.
    {
        const int sq1 = t & 15;        // c-quad
        const int pg1 = t >> 4;        // 0..31
        const int arow1 = wid*16 + (lane & 7) + ((lane >> 3) & 1)*8;
        const int acol1 = (lane >> 4) * 16;

        float acc1[3][4];
        #pragma unroll
        for (int nt = 0; nt < 3; nt++)
            #pragma unroll
            for (int r = 0; r < 4; r++) acc1[nt][r] = 0.f;

        #pragma unroll 1
        for (int k = 0; k < 9; k++) {
            __syncthreads();
            const int ky = k/3 - 1, kx = k%3 - 1;

            #pragma unroll
            for (int j = 0; j < 8; j++) {
                int p = pg1 + 32*j;
                int h = h0 + (p >> 5), w = w0 + (p & 31);
                int hy = h + ky, wx = w + kx;
                float4 v = make_float4(0.f, 0.f, 0.f, 0.f);
                if (hy >= 0 && hy < Hc && wx >= 0 && wx < Wc)
                    v = *(const float4*)(xtb + (size_t)(hy*Wc + wx)*64 + sq1*4);
                uint2 hv, lv;
                split2(v.x, v.y, hv.x, lv.x);
                split2(v.z, v.w, hv.y, lv.y);
                unsigned sw = sw128((unsigned)(p*128 + sq1*8));
                *(uint2*)(smem + SM_A(0)   + sw) = hv;
                *(uint2*)(smem + SM_ALO(0) + sw) = lv;
            }
            __syncthreads();

            const uint2* bfh = g_bfragO_hi + (size_t)k*384;
            const uint2* bfl = g_bfragO_lo + (size_t)k*384;
            #pragma unroll
            for (int ks = 0; ks < 4; ks++) {
                uint32_t ah[4], al[4];
                unsigned off = sw128((unsigned)(arow1*128 + acol1 + ks*32));
                ldsm4(ah, sbase + SM_A(0)   + off);
                ldsm4(al, sbase + SM_ALO(0) + off);
                uint2 bh[3], bl[3];
                #pragma unroll
                for (int nt = 0; nt < 3; nt++) {
                    bh[nt] = __ldg(&bfh[(ks*3 + nt)*32 + lane]);
                    bl[nt] = __ldg(&bfl[(ks*3 + nt)*32 + lane]);
                }
                #pragma unroll
                for (int nt = 0; nt < 3; nt++) {
                    mma16816(acc1[nt], ah, bh[nt]);
                    mma16816(acc1[nt], al, bh[nt]);
                    mma16816(acc1[nt], ah, bl[nt]);
                }
            }
        }

        #pragma unroll
        for (int nt = 0; nt < 3; nt++) {
            int o0 = nt*8 + ocol;
            if (o0 < 18) {
                float bo0 = b_off[o0], bo1 = b_off[o0+1];
                #pragma unroll
                for (int half = 0; half < 2; half++) {
                    int p = wid*16 + prow + half*8;
                    s_off[o0*256 + p]     = acc1[nt][half*2]   + bo0;
                    s_off[(o0+1)*256 + p] = acc1[nt][half*2+1] + bo1;
                }
            }
        }
    }
    __syncthreads();   // s_off complete; A buffers free

    // ============================ phase 2: pipelined =======================
    if (t < 256) {
        // ---------------- producers (warps 0-7) ----------------
        const int sq = t & 15;      // c-quad
        const int pg = t >> 4;      // pixel phase (0..15)
        const int mh = h0 + (t >> 5), mw = w0 + (t & 31);   // meta pixel = t

        #pragma unroll 1
        for (int k = 0; k < 9; k++) {
            const int bb = k & 1;
            if (k >= 2) BAR_SYNC_ALL(3 + bb);      // EMPTY[bb]

            // meta for pixel t into buffer bb
            {
                float oy = s_off[(2*k  )*256 + t];
                float ox = s_off[(2*k+1)*256 + t];
                float py = (float)(mh + k/3 - 1) + oy;
                float px = (float)(mw + k%3 - 1) + ox;
                float y0 = floorf(py), x0 = floorf(px);
                #pragma unroll
                for (int d = 0; d < 4; d++) {
                    float iy = y0 + (float)(d >> 1);
                    float ix = x0 + (float)(d & 1);
                    float wgt = (1.f - fabsf(py - iy)) * (1.f - fabsf(px - ix));
                    bool valid = (iy >= 0.f) && (iy <= (float)(Hc-1)) &&
                                 (ix >= 0.f) && (ix <= (float)(Wc-1));
                    s_wt[bb*1024 + d*256 + t] = valid ? wgt : 0.f;
                    int iyc = min(max((int)iy, 0), Hc-1);
                    int ixc = min(max((int)ix, 0), Wc-1);
                    s_idx[bb*1024 + d*256 + t] = (iyc*Wc + ixc) * 64;
                }
            }
            BAR_SYNC_PROD();                       // meta[bb] visible to producers

            // gather + convert into A[bb]
            #pragma unroll 4
            for (int j = 0; j < 16; j++) {
                int p = pg + 16*j;
                float ax = 0.f, ay = 0.f, az = 0.f, aw = 0.f;
                #pragma unroll
                for (int d = 0; d < 4; d++) {
                    float wg = s_wt[bb*1024 + d*256 + p];
                    const float4 v = *(const float4*)(xtb +
                        (size_t)s_idx[bb*1024 + d*256 + p] + sq*4);
                    ax += wg*v.x; ay += wg*v.y; az += wg*v.z; aw += wg*v.w;
                }
                uint2 hv, lv;
                split2(ax, ay, hv.x, lv.x);
                split2(az, aw, hv.y, lv.y);
                unsigned sw = sw128((unsigned)(p*128 + sq*8));
                *(uint2*)(smem + SM_A(bb)   + sw) = hv;
                *(uint2*)(smem + SM_ALO(bb) + sw) = lv;
            }
            BAR_ARRIVE_ALL(1 + bb);                // FULL[bb]
        }
    } else {
        // ---------------- consumers (warps 8-15) ----------------
        const int cw = wid - 8;
        const int arow = cw*32 + (lane & 7) + ((lane >> 3) & 1)*8;   // + mt*16
        const int acol = (lane >> 4) * 16;                           // + ks*32

        float acc[2][8][4];
        #pragma unroll
        for (int mt = 0; mt < 2; mt++)
            #pragma unroll
            for (int nt = 0; nt < 8; nt++)
                #pragma unroll
                for (int r = 0; r < 4; r++) acc[mt][nt][r] = 0.f;

        #pragma unroll 1
        for (int k = 0; k < 9; k++) {
            const int bb = k & 1;
            BAR_SYNC_ALL(1 + bb);                  // FULL[bb]

            const uint2* bfh = g_bfrag_hi + (size_t)k*1024;
            const uint2* bfl = g_bfrag_lo + (size_t)k*1024;
            #pragma unroll
            for (int ks = 0; ks < 4; ks++) {
                uint32_t ah[2][4], al[2][4];
                #pragma unroll
                for (int mt = 0; mt < 2; mt++) {
                    unsigned off = sw128((unsigned)((arow + mt*16)*128 + acol + ks*32));
                    ldsm4(ah[mt], sbase + SM_A(bb)   + off);
                    ldsm4(al[mt], sbase + SM_ALO(bb) + off);
                }
                uint2 bh[8], bl[8];
                #pragma unroll
                for (int nt = 0; nt < 8; nt++) {
                    bh[nt] = __ldg(&bfh[(ks*8 + nt)*32 + lane]);
                    bl[nt] = __ldg(&bfl[(ks*8 + nt)*32 + lane]);
                }
                #pragma unroll
                for (int mt = 0; mt < 2; mt++)
                    #pragma unroll
                    for (int nt = 0; nt < 8; nt++) {
                        mma16816(acc[mt][nt], ah[mt], bh[nt]);
                        mma16816(acc[mt][nt], al[mt], bh[nt]);
                        mma16816(acc[mt][nt], ah[mt], bl[nt]);
                    }
            }
            if (k <= 6) BAR_ARRIVE_ALL(3 + bb);    // EMPTY[bb]
        }

        // epilogue: BN fold + ReLU, direct stores
        #pragma unroll
        for (int nt = 0; nt < 8; nt++) {
            int o0 = nt*8 + ocol;
            float iv0 = g_inv[o0],   bs0 = g_bias2[o0];
            float iv1 = g_inv[o0+1], bs1 = g_bias2[o0+1];
            #pragma unroll
            for (int mt = 0; mt < 2; mt++) {
                #pragma unroll
                for (int half = 0; half < 2; half++) {
                    int p = cw*32 + mt*16 + prow + half*8;
                    int h = h0 + (p >> 5), w = w0 + (p & 31);
                    float* ob = out + ((size_t)b*64*Hc + h)*Wc + w;
                    float y0 = acc[mt][nt][half*2]   * iv0 + bs0;
                    float y1 = acc[mt][nt][half*2+1] * iv1 + bs1;
                    ob[(size_t)o0*HWc]     = fmaxf(y0, 0.f);
                    ob[(size_t)(o0+1)*HWc] = fmaxf(y1, 0.f);
                }
            }
        }
    }
}

// ---------------------------------------------------------------------------
extern "C" void kernel_launch(void* const* d_in, const int* in_sizes, int n_in,
                              void* d_out, int out_size) {
    const float* x        = (const float*)d_in[0];
    const float* w_off    = (const float*)d_in[1];
    const float* b_off    = (const float*)d_in[2];
    const float* w_dcn    = (const float*)d_in[3];
    const float* b_dcn    = (const float*)d_in[4];
    const float* gamma    = (const float*)d_in[5];
    const float* beta     = (const float*)d_in[6];
    const float* run_mean = (const float*)d_in[7];
    const float* run_var  = (const float*)d_in[8];
    float* out = (float*)d_out;

    cudaFuncSetAttribute(fused_kernel,
                         cudaFuncAttributeMaxDynamicSharedMemorySize, SM_TOTAL);

    dim3 grid(Wc/32, Hc/8, Bc);
    prep_kernel<<<dim3(9, 4), 256>>>(w_dcn, b_dcn, w_off, gamma, beta, run_mean, run_var);
    transpose_kernel<<<dim3(HWc/64, Bc), 256>>>(x);
    fused_kernel<<<grid, 512, SM_TOTAL>>>(b_off, out);
}

// round 12
// speedup vs baseline: 1.0307x; 1.0307x over previous
#include <cuda_runtime.h>
#include <cuda_bf16.h>
#include <cstdint>

#define Bc 8
#define Hc 160
#define Wc 160
#define HWc (Hc*Wc)

typedef unsigned long long ull;
typedef unsigned short ushort_t;

// scratch (no allocations allowed)
__device__ float g_xt[(size_t)Bc*HWc*64];        // x transposed to [b][hw][c] fp32
__device__ ushort_t g_xbh[(size_t)Bc*HWc*64];    // x bf16 hi, [b][hw][c]
__device__ ushort_t g_xbl[(size_t)Bc*HWc*64];    // x bf16 lo residual
__device__ uint2 g_bfrag_hi[9*4*8*32];           // main B frags bf16 hi [k][kstep][ntile][lane]
__device__ uint2 g_bfrag_lo[9*4*8*32];           // main B frags bf16 lo
__device__ uint2 g_bfragO_hi[9*4*3*32];          // offset-conv B frags hi
__device__ uint2 g_bfragO_lo[9*4*3*32];          // offset-conv B frags lo
__device__ float g_inv[64];
__device__ float g_bias2[64];

__device__ __forceinline__ uint32_t smem_u32(const void* p) {
    uint32_t a;
    asm("{ .reg .u64 t; cvta.to.shared.u64 t, %1; cvt.u32.u64 %0, t; }" : "=r"(a) : "l"(p));
    return a;
}
__device__ __forceinline__ unsigned sw128(unsigned off) {
    return off ^ ((off >> 3) & 0x70);
}
__device__ __forceinline__ void ldsm4(uint32_t* r, uint32_t addr) {
    asm volatile("ldmatrix.sync.aligned.m8n8.x4.shared.b16 {%0,%1,%2,%3}, [%4];"
        : "=r"(r[0]), "=r"(r[1]), "=r"(r[2]), "=r"(r[3]) : "r"(addr));
}
__device__ __forceinline__ void mma16816(float* c, const uint32_t* a, const uint2 b) {
    asm volatile("mma.sync.aligned.m16n8k16.row.col.f32.bf16.bf16.f32 "
        "{%0,%1,%2,%3}, {%4,%5,%6,%7}, {%8,%9}, {%0,%1,%2,%3};"
        : "+f"(c[0]), "+f"(c[1]), "+f"(c[2]), "+f"(c[3])
        : "r"(a[0]), "r"(a[1]), "r"(a[2]), "r"(a[3]), "r"(b.x), "r"(b.y));
}
// pack (x,y) -> bf16x2 hi + residual bf16x2 lo
__device__ __forceinline__ void split2(float x, float y, uint32_t& hv, uint32_t& lv) {
    asm("cvt.rn.bf16x2.f32 %0, %1, %2;" : "=r"(hv) : "f"(y), "f"(x));
    float hx = __uint_as_float(hv << 16);
    float hy = __uint_as_float(hv & 0xffff0000u);
    float rx = x - hx, ry = y - hy;
    asm("cvt.rn.bf16x2.f32 %0, %1, %2;" : "=r"(lv) : "f"(ry), "f"(rx));
}

// fused kernel dynamic smem layout (bytes), M=128 tile
#define SM_A     0                         // A hi: 128 rows x 128 B (SW128)
#define SM_ALO   16384                     // A lo
#define SM_OFF   32768                     // float[18][128]
#define SM_WT    41984                     // float[2][4][128] meta, double-buffered
#define SM_IDX   46080                     // int[2][4][128]
#define SM_TOTAL 50176

// ---------------------------------------------------------------------------
// prep: fold BN; split w_dcn AND w_off to bf16 hi/lo in mma B-fragment layout.
// ---------------------------------------------------------------------------
__global__ void prep_kernel(const float* __restrict__ w_dcn,
                            const float* __restrict__ b_dcn,
                            const float* __restrict__ w_off,
                            const float* __restrict__ gamma,
                            const float* __restrict__ beta,
                            const float* __restrict__ run_mean,
                            const float* __restrict__ run_var) {
    int k = blockIdx.x;
    int part = blockIdx.y;
    int t = threadIdx.x;
    {
        int e = part*256 + t;
        int lane  = e & 31;
        int ntile = (e >> 5) & 7;
        int kstep = e >> 8;
        int o  = ntile*8 + (lane >> 2);
        int c0 = kstep*16 + 2*(lane & 3);
        float w00 = w_dcn[o*576 + (c0  )*9 + k];
        float w01 = w_dcn[o*576 + (c0+1)*9 + k];
        float w10 = w_dcn[o*576 + (c0+8)*9 + k];
        float w11 = w_dcn[o*576 + (c0+9)*9 + k];
        uint32_t h0, l0, h1, l1;
        split2(w00, w01, h0, l0);
        split2(w10, w11, h1, l1);
        int idx = ((k*4 + kstep)*8 + ntile)*32 + lane;
        g_bfrag_hi[idx] = make_uint2(h0, h1);
        g_bfrag_lo[idx] = make_uint2(l0, l1);
    }
    {
        int e = part*256 + t;
        if (e < 384) {
            int lane  = e & 31;
            int ntile = (e >> 5) % 3;
            int kstep = e / 96;
            int o  = ntile*8 + (lane >> 2);
            int c0 = kstep*16 + 2*(lane & 3);
            float w00 = 0.f, w01 = 0.f, w10 = 0.f, w11 = 0.f;
            if (o < 18) {
                w00 = w_off[o*576 + (c0  )*9 + k];
                w01 = w_off[o*576 + (c0+1)*9 + k];
                w10 = w_off[o*576 + (c0+8)*9 + k];
                w11 = w_off[o*576 + (c0+9)*9 + k];
            }
            uint32_t h0, l0, h1, l1;
            split2(w00, w01, h0, l0);
            split2(w10, w11, h1, l1);
            int idx = ((k*4 + kstep)*3 + ntile)*32 + lane;
            g_bfragO_hi[idx] = make_uint2(h0, h1);
            g_bfragO_lo[idx] = make_uint2(l0, l1);
        }
    }
    if (k == 0 && part == 0 && t < 64) {
        float iv = gamma[t] * rsqrtf(run_var[t] + 1e-5f);
        g_inv[t] = iv;
        g_bias2[t] = b_dcn[t]*iv + beta[t] - run_mean[t]*iv;
    }
}

// ---------------------------------------------------------------------------
// transpose x: [b][c][hw] -> [b][hw][c] fp32 + pre-split bf16 hi/lo
// ---------------------------------------------------------------------------
__global__ __launch_bounds__(256) void transpose_kernel(const float* __restrict__ x) {
    __shared__ float sm[64*65];
    int b   = blockIdx.y;
    int hw0 = blockIdx.x * 64;
    int t   = threadIdx.x;
    const float* xb = x + (size_t)b*64*HWc;
    #pragma unroll
    for (int i = 0; i < 16; i++) {
        int c = i*4 + (t>>6);
        int j = t & 63;
        sm[c*65 + j] = xb[(size_t)c*HWc + hw0 + j];
    }
    __syncthreads();
    float* ob = g_xt + ((size_t)b*HWc + hw0)*64;
    ushort_t* oh = g_xbh + ((size_t)b*HWc + hw0)*64;
    ushort_t* ol = g_xbl + ((size_t)b*HWc + hw0)*64;
    #pragma unroll
    for (int i = 0; i < 16; i++) {
        int hw = i*4 + (t>>6);
        int c  = t & 63;
        float v = sm[c*65 + hw];
        ob[hw*64 + c] = v;
        __nv_bfloat16 hb = __float2bfloat16_rn(v);
        float lof = v - __bfloat162float(hb);
        oh[hw*64 + c] = __bfloat16_as_ushort(hb);
        ol[hw*64 + c] = __bfloat16_as_ushort(__float2bfloat16_rn(lof));
    }
}

// ---------------------------------------------------------------------------
// fused, M=128 tile (4 rows x 32 cols), 256 threads, 3 CTAs/SM:
// [phase 1] offset conv implicit GEMM (pre-split bf16 A copy, 3-pass mma)
// [phase 2] deform sampling + 3-pass bf16 GEMM + BN + ReLU (round-9 serial
// structure, meta double-buffered & overlapped with mma).
// ---------------------------------------------------------------------------
__global__ __launch_bounds__(256, 3) void fused_kernel(
        const float* __restrict__ b_off,
        float* __restrict__ out) {
    extern __shared__ char smem[];
    const uint32_t sbase = smem_u32(smem);
    float* s_off = (float*)(smem + SM_OFF);   // [18][128]
    float* s_wt  = (float*)(smem + SM_WT);    // [2][4][128]
    int*   s_idx = (int*)(smem + SM_IDX);     // [2][4][128]

    const int t    = threadIdx.x;
    const int wid  = t >> 5;
    const int lane = t & 31;
    const int b    = blockIdx.z;
    const int h0   = blockIdx.y * 4;
    const int w0   = blockIdx.x * 32;
    const int sq   = t & 15;       // c-quad
    const int pg   = t >> 4;       // px phase (0..15)

    const float* xtb = g_xt + (size_t)b*HWc*64;
    const ushort_t* xbh = g_xbh + (size_t)b*HWc*64;
    const ushort_t* xbl = g_xbl + (size_t)b*HWc*64;

    // warp handles rows [wid*16, wid*16+16)
    const int arow = wid*16 + (lane & 7) + ((lane >> 3) & 1)*8;
    const int acol = (lane >> 4) * 16;      // + ks*32
    const int prow = lane >> 2;
    const int ocol = 2*(lane & 3);

    // ============================ phase 1: offset conv =====================
    {
        float acc1[3][4];
        #pragma unroll
        for (int nt = 0; nt < 3; nt++)
            #pragma unroll
            for (int r = 0; r < 4; r++) acc1[nt][r] = 0.f;

        #pragma unroll 1
        for (int k = 0; k < 9; k++) {
            __syncthreads();   // A free
            const int ky = k/3 - 1, kx = k%3 - 1;

            // A tile copy from pre-split bf16 (128 px x 16 quads / 256 thr)
            #pragma unroll
            for (int j = 0; j < 8; j++) {
                int p = pg + 16*j;
                int h = h0 + (p >> 5), w = w0 + (p & 31);
                int hy = h + ky, wx = w + kx;
                uint2 hv = make_uint2(0u, 0u), lv = make_uint2(0u, 0u);
                if (hy >= 0 && hy < Hc && wx >= 0 && wx < Wc) {
                    size_t idx = (size_t)(hy*Wc + wx)*64 + sq*4;
                    hv = *(const uint2*)(xbh + idx);
                    lv = *(const uint2*)(xbl + idx);
                }
                unsigned sw = sw128((unsigned)(p*128 + sq*8));
                *(uint2*)(smem + SM_A   + sw) = hv;
                *(uint2*)(smem + SM_ALO + sw) = lv;
            }
            __syncthreads();

            const uint2* bfh = g_bfragO_hi + (size_t)k*384;
            const uint2* bfl = g_bfragO_lo + (size_t)k*384;
            #pragma unroll
            for (int ks = 0; ks < 4; ks++) {
                uint32_t ah[4], al[4];
                unsigned off = sw128((unsigned)(arow*128 + acol + ks*32));
                ldsm4(ah, sbase + SM_A   + off);
                ldsm4(al, sbase + SM_ALO + off);
                #pragma unroll
                for (int nt = 0; nt < 3; nt++) {
                    uint2 bh = __ldg(&bfh[(ks*3 + nt)*32 + lane]);
                    uint2 bl = __ldg(&bfl[(ks*3 + nt)*32 + lane]);
                    mma16816(acc1[nt], ah, bh);
                    mma16816(acc1[nt], al, bh);
                    mma16816(acc1[nt], ah, bl);
                }
            }
        }

        // epilogue: offsets (+bias) into smem [oc][p]
        #pragma unroll
        for (int nt = 0; nt < 3; nt++) {
            int o0 = nt*8 + ocol;
            if (o0 < 18) {
                float bo0 = b_off[o0], bo1 = b_off[o0+1];
                #pragma unroll
                for (int half = 0; half < 2; half++) {
                    int p = wid*16 + prow + half*8;
                    s_off[o0*128 + p]     = acc1[nt][half*2]   + bo0;
                    s_off[(o0+1)*128 + p] = acc1[nt][half*2+1] + bo1;
                }
            }
        }
    }
    __syncthreads();   // s_off complete; A free

    // ============================ phase 2: deform GEMM =====================
    float acc[8][4];
    #pragma unroll
    for (int nt = 0; nt < 8; nt++)
        #pragma unroll
        for (int r = 0; r < 4; r++) acc[nt][r] = 0.f;

    const int mh = h0 + (t >> 5), mw = w0 + (t & 31);   // meta px = t (t<128)
    #define COMPUTE_META(k) do {                                              \
        if (t < 128) {                                                        \
            int buf = (k) & 1;                                                \
            float oy = s_off[(2*(k)  )*128 + t];                              \
            float ox = s_off[(2*(k)+1)*128 + t];                              \
            float py = (float)(mh + (k)/3 - 1) + oy;                          \
            float px = (float)(mw + (k)%3 - 1) + ox;                          \
            float y0 = floorf(py), x0 = floorf(px);                           \
            _Pragma("unroll")                                                 \
            for (int d = 0; d < 4; d++) {                                     \
                float iy = y0 + (float)(d >> 1);                              \
                float ix = x0 + (float)(d & 1);                               \
                float wgt = (1.f - fabsf(py - iy)) * (1.f - fabsf(px - ix));  \
                bool valid = (iy >= 0.f) && (iy <= (float)(Hc-1)) &&          \
                             (ix >= 0.f) && (ix <= (float)(Wc-1));            \
                s_wt[buf*512 + d*128 + t] = valid ? wgt : 0.f;                \
                int iyc = min(max((int)iy, 0), Hc-1);                         \
                int ixc = min(max((int)ix, 0), Wc-1);                         \
                s_idx[buf*512 + d*128 + t] = (iyc*Wc + ixc) * 64;             \
            }                                                                 \
        }                                                                     \
    } while (0)

    COMPUTE_META(0);

    #pragma unroll 1
    for (int k = 0; k < 9; k++) {
        __syncthreads();   // A free (prev mma done) + meta[k] ready
        const int buf = k & 1;

        // sampling: gather channel-last, split to bf16 hi/lo, store swizzled
        #pragma unroll
        for (int j = 0; j < 8; j++) {
            int p = pg + 16*j;
            float ax = 0.f, ay = 0.f, az = 0.f, aw = 0.f;
            #pragma unroll
            for (int d = 0; d < 4; d++) {
                float wg = s_wt[buf*512 + d*128 + p];
                const float4 v = *(const float4*)(xtb +
                    (size_t)s_idx[buf*512 + d*128 + p] + sq*4);
                ax += wg*v.x; ay += wg*v.y; az += wg*v.z; aw += wg*v.w;
            }
            uint2 hv, lv;
            split2(ax, ay, hv.x, lv.x);
            split2(az, aw, hv.y, lv.y);
            unsigned sw = sw128((unsigned)(p*128 + sq*8));
            *(uint2*)(smem + SM_A   + sw) = hv;
            *(uint2*)(smem + SM_ALO + sw) = lv;
        }
        __syncthreads();   // A ready

        // overlap: meta for k+1 (other buffer) hidden under mma issue
        if (k < 8) COMPUTE_META(k + 1);

        // GEMM: per k-step ldsm A hi/lo + per-nt B hi/lo ldg, 3-pass mma
        const uint2* bfh = g_bfrag_hi + (size_t)k*1024;
        const uint2* bfl = g_bfrag_lo + (size_t)k*1024;
        #pragma unroll
        for (int ks = 0; ks < 4; ks++) {
            uint32_t ah[4], al[4];
            unsigned off = sw128((unsigned)(arow*128 + acol + ks*32));
            ldsm4(ah, sbase + SM_A   + off);
            ldsm4(al, sbase + SM_ALO + off);
            #pragma unroll
            for (int nt = 0; nt < 8; nt++) {
                uint2 bh = __ldg(&bfh[(ks*8 + nt)*32 + lane]);
                uint2 bl = __ldg(&bfl[(ks*8 + nt)*32 + lane]);
                mma16816(acc[nt], ah, bh);
                mma16816(acc[nt], al, bh);
                mma16816(acc[nt], ah, bl);
            }
        }
    }

    // epilogue: BN fold + ReLU, direct stores (warp wid: rows wid*16..+16)
    #pragma unroll
    for (int nt = 0; nt < 8; nt++) {
        int o0 = nt*8 + ocol;
        float iv0 = g_inv[o0],   bs0 = g_bias2[o0];
        float iv1 = g_inv[o0+1], bs1 = g_bias2[o0+1];
        #pragma unroll
        for (int half = 0; half < 2; half++) {
            int p = wid*16 + prow + half*8;
            int h = h0 + (p >> 5), w = w0 + (p & 31);
            float* ob = out + ((size_t)b*64*Hc + h)*Wc + w;
            float y0 = acc[nt][half*2]   * iv0 + bs0;
            float y1 = acc[nt][half*2+1] * iv1 + bs1;
            ob[(size_t)o0*HWc]     = fmaxf(y0, 0.f);
            ob[(size_t)(o0+1)*HWc] = fmaxf(y1, 0.f);
        }
    }
}

// ---------------------------------------------------------------------------
extern "C" void kernel_launch(void* const* d_in, const int* in_sizes, int n_in,
                              void* d_out, int out_size) {
    const float* x        = (const float*)d_in[0];
    const float* w_off    = (const float*)d_in[1];
    const float* b_off    = (const float*)d_in[2];
    const float* w_dcn    = (const float*)d_in[3];
    const float* b_dcn    = (const float*)d_in[4];
    const float* gamma    = (const float*)d_in[5];
    const float* beta     = (const float*)d_in[6];
    const float* run_mean = (const float*)d_in[7];
    const float* run_var  = (const float*)d_in[8];
    float* out = (float*)d_out;

    cudaFuncSetAttribute(fused_kernel,
                         cudaFuncAttributeMaxDynamicSharedMemorySize, SM_TOTAL);

    dim3 grid(Wc/32, Hc/4, Bc);
    prep_kernel<<<dim3(9, 4), 256>>>(w_dcn, b_dcn, w_off, gamma, beta, run_mean, run_var);
    transpose_kernel<<<dim3(HWc/64, Bc), 256>>>(x);
    fused_kernel<<<grid, 256, SM_TOTAL>>>(b_off, out);
}